// round 15
// baseline (speedup 1.0000x reference)
#include <cuda_runtime.h>
#include <math.h>

#define Bv  8
#define Tv  32
#define Nv  500
#define Fv  64
#define Hv  128
#define Ev  8000
#define BT  256            // B*T
#define BTN 128000         // B*T*N
#define NNZ (Ev + Nv)

// ---------------- scratch (static device globals: allowed) ----------------
__device__ float  g_xf [BTN * Hv];   // x @ W_gcn            (bt, n, h)
__device__ float  g_res[BTN * Hv];   // x @ W_res + b_res    (bt, n, h)
__device__ float  g_hg [BTN * Hv];   // gelu(gcn agg + b)    (bt, n, h)
__device__ float  g_wt [384 * Hv];   // W_temp transposed: [(i*3+k)][o]
__device__ float  g_deg [Nv];        // zero-init (BSS); re-zeroed each run
__device__ int    g_cnt [Nv];        // zero-init (BSS); re-zeroed each run
__device__ int    g_rowptr[Nv + 1];
__device__ float2 g_ev[NNZ];         // {norm, __int_as_float(src)} CSR by dst

// ---------------- helpers ----------------
__device__ __forceinline__ unsigned long long pack2(float lo, float hi) {
    unsigned long long r;
    asm("mov.b64 %0, {%1, %2};" : "=l"(r) : "f"(lo), "f"(hi));
    return r;
}
__device__ __forceinline__ void unpack2(unsigned long long v, float& lo, float& hi) {
    asm("mov.b64 {%0, %1}, %2;" : "=f"(lo), "=f"(hi) : "l"(v));
}
__device__ __forceinline__ void fma2(unsigned long long& d, unsigned long long a,
                                     unsigned long long b) {
    asm("fma.rn.f32x2 %0, %1, %2, %0;" : "+l"(d) : "l"(a), "l"(b));
}
__device__ __forceinline__ float gelu_exact(float x) {
    return 0.5f * x * (1.0f + erff(x * 0.7071067811865476f));
}
__device__ __forceinline__ int detect64(const void* ei) {
    const long long* p = (const long long*)ei;
    int ok64 = 1;
#pragma unroll
    for (int j = 0; j < 8; ++j) {
        long long v = p[j];
        if (v < 0 || v >= Nv) ok64 = 0;
    }
    return ok64;
}
__device__ __forceinline__ int load_idx(const void* ei, int i, int is64) {
    long long v;
    if (is64) v = ((const long long*)ei)[i];
    else      v = ((const int*)ei)[i];
    if (v < 0) v = 0;
    if (v >= Nv) v = Nv - 1;
    return (int)v;
}

// ---------------- K2 (launch #1): fused input projections, f32x2 packed ---
__global__ __launch_bounds__(128) void k_inproj(
    const float* __restrict__ x, const float* __restrict__ Wg,
    const float* __restrict__ Wr, const float* __restrict__ br) {
    __shared__ float sx[8][64];
    int h = threadIdx.x;
    unsigned long long wp[64];
#pragma unroll
    for (int i = 0; i < 64; ++i) wp[i] = pack2(Wg[i * Hv + h], Wr[i * Hv + h]);
    float brh = br[h];
    int row0 = blockIdx.x * 128;
#pragma unroll 1
    for (int c = 0; c < 16; ++c) {
        int rbase = row0 + c * 8;
        __syncthreads();
        for (int j = h; j < 512; j += 128)
            sx[j >> 6][j & 63] = x[(rbase + (j >> 6)) * Fv + (j & 63)];
        __syncthreads();
#pragma unroll
        for (int r = 0; r < 8; ++r) {
            unsigned long long acc = 0ULL;
#pragma unroll
            for (int i = 0; i < 64; i += 4) {
                float4 xv = *(const float4*)&sx[r][i];
                fma2(acc, pack2(xv.x, xv.x), wp[i + 0]);
                fma2(acc, pack2(xv.y, xv.y), wp[i + 1]);
                fma2(acc, pack2(xv.z, xv.z), wp[i + 2]);
                fma2(acc, pack2(xv.w, xv.w), wp[i + 3]);
            }
            float ag, ar; unpack2(acc, ag, ar);
            int row = rbase + r;
            g_xf [row * Hv + h] = ag;
            g_res[row * Hv + h] = ar + brh;
        }
    }
}

// ---------------- P1 (launch #2): degree + counts; tail blocks wtrans -----
__global__ void p_deg(const void* __restrict__ ei, const float* __restrict__ ew,
                      const float* __restrict__ Wt) {
    if (blockIdx.x >= 63) {
        int idx = (blockIdx.x - 63) * 128 + threadIdx.x;   // < 49152
        if (idx < 128 * 384) {
            int o = idx / 384, m = idx % 384;
            g_wt[m * Hv + o] = Wt[o * 384 + m];
        }
        return;
    }
    __shared__ int sis64;
    if (threadIdx.x == 0) sis64 = detect64(ei);
    __syncthreads();
    int is64 = sis64;
    int e = blockIdx.x * 128 + threadIdx.x;
    if (e >= Ev) return;
    int dst = load_idx(ei, Ev + e, is64);
    atomicAdd(&g_deg[dst], ew[e]);
    atomicAdd(&g_cnt[dst], 1);
}

// ---------------- P2 (launch #3): scan + CSR fill, single block -----------
__global__ __launch_bounds__(512) void p_scanfill(
    const void* __restrict__ ei, const float* __restrict__ ew) {
    __shared__ int   s[512];
    __shared__ float sdinv[Nv];
    __shared__ int   sfill[Nv];
    __shared__ int   sis64;
    int tid = threadIdx.x;
    if (tid == 0) sis64 = detect64(ei);

    int c = 0;
    if (tid < Nv) {
        float d = g_deg[tid] + 1.0f;           // + self loop weight
        sdinv[tid] = rsqrtf(d);
        c = g_cnt[tid] + 1;                    // + self loop edge
    }
    s[tid] = c;
    __syncthreads();
    for (int off = 1; off < 512; off <<= 1) {
        int v = (tid >= off) ? s[tid - off] : 0;
        __syncthreads();
        s[tid] += v;
        __syncthreads();
    }
    if (tid < Nv) {
        g_rowptr[tid + 1] = s[tid];
        sfill[tid] = s[tid] - c;
        if (tid == 0) g_rowptr[0] = 0;
        g_deg[tid] = 0.0f;                     // reset for next graph replay
        g_cnt[tid] = 0;
    }
    __syncthreads();
    int is64 = sis64;
    for (int e = tid; e < NNZ; e += 512) {
        int src, dst; float w;
        if (e < Ev) { src = load_idx(ei, e, is64); dst = load_idx(ei, Ev + e, is64); w = ew[e]; }
        else        { src = dst = e - Ev; w = 1.0f; }
        float v = sdinv[src] * w * sdinv[dst];
        int pos = atomicAdd(&sfill[dst], 1);
        if (pos >= 0 && pos < NNZ)
            g_ev[pos] = make_float2(v, __int_as_float(src));
    }
}

// ---------------- K3 (launch #4, PROFILED): GCN v6 warp-per-row gather ----
// 32 channels/block tile, smem sxf[500][32] = 64KB dynamic. One warp per dst
// row, one lane per channel. Per edge: uniform LDG.64 (broadcast) +
// conflict-free LDS.32 (1 wavefront / 32 MACs) + 1 FFMA.
__global__ __launch_bounds__(128) void k_gcn(const float* __restrict__ bg) {
    extern __shared__ __align__(16) float sxf[];    // [500][32]
    int bt = blockIdx.x;
    int hbase = blockIdx.y * 32;
    int tid = threadIdx.x;
    int lane = tid & 31, warp = tid >> 5;
    const float* xsrc = g_xf + (size_t)bt * (Nv * Hv) + hbase;
    for (int idx = tid; idx < Nv * 32; idx += 128) {
        int n = idx >> 5, cc = idx & 31;
        sxf[idx] = xsrc[n * Hv + cc];
    }
    __syncthreads();
    float bgv = bg[hbase + lane];
    float* dst = g_hg + (size_t)bt * (Nv * Hv) + hbase;
#pragma unroll 1
    for (int n = warp; n < Nv; n += 4) {
        int rs = g_rowptr[n], re = g_rowptr[n + 1];
        float acc0 = 0.0f, acc1 = 0.0f;
        int e = rs;
#pragma unroll 1
        for (; e + 1 < re; e += 2) {
            float2 ev0 = g_ev[e];
            float2 ev1 = g_ev[e + 1];
            acc0 += ev0.x * sxf[__float_as_int(ev0.y) * 32 + lane];
            acc1 += ev1.x * sxf[__float_as_int(ev1.y) * 32 + lane];
        }
        if (e < re) {
            float2 ev0 = g_ev[e];
            acc0 += ev0.x * sxf[__float_as_int(ev0.y) * 32 + lane];
        }
        dst[n * Hv + lane] = gelu_exact(acc0 + acc1 + bgv);
    }
}

// ---------------- K4 (launch #5): conv + gelu + residual + LayerNorm ------
// v4 (R11 best): ONE (b,n) per block; t-dim packed into f32x2 lanes (t, t+16).
__global__ __launch_bounds__(128) void k_conv(
    const float* __restrict__ btmp,
    const float* __restrict__ lnw, const float* __restrict__ lnb,
    float* __restrict__ out) {
    __shared__ __align__(16) char smbuf[18432];
    __shared__ float smu[32], srs[32];
    int o = threadIdx.x;
    int bn = blockIdx.x;
    int b = bn / Nv, n = bn % Nv;

    // ---- stage packed input pairs ----
    {
        float xv[32];
        const float* src = g_hg + ((size_t)(b * Tv) * Nv + n) * Hv + o;
#pragma unroll
        for (int t = 0; t < 32; ++t) xv[t] = src[(size_t)t * Nv * Hv];
        float2* sp = (float2*)smbuf;          // [s][128]
#pragma unroll
        for (int s = 0; s < 18; ++s) {
            float lo = (s == 0)  ? 0.0f : xv[s - 1];
            float hi = (s == 17) ? 0.0f : xv[s + 15];
            sp[s * 128 + o] = make_float2(lo, hi);
        }
    }
    __syncthreads();

    unsigned long long acc[16];
#pragma unroll
    for (int t = 0; t < 16; ++t) acc[t] = 0ULL;

    const float* wtp = g_wt + o;               // [(m)][o], lane-coalesced
    const ulonglong2* colbase = (const ulonglong2*)smbuf;   // [s][64]
#pragma unroll 1
    for (int q = 0; q < 64; ++q) {             // i = 2q, 2q+1
        int m = q * 6;
        float wa0 = wtp[(m + 0) * Hv];
        float wa1 = wtp[(m + 1) * Hv];
        float wa2 = wtp[(m + 2) * Hv];
        float wb0 = wtp[(m + 3) * Hv];
        float wb1 = wtp[(m + 4) * Hv];
        float wb2 = wtp[(m + 5) * Hv];
        unsigned long long w0a = pack2(wa0, wa0), w1a = pack2(wa1, wa1),
                           w2a = pack2(wa2, wa2);
        unsigned long long w0b = pack2(wb0, wb0), w1b = pack2(wb1, wb1),
                           w2b = pack2(wb2, wb2);
        const ulonglong2* col = colbase + q;    // stride 64 per s
        ulonglong2 v0 = col[0];                 // s = t + kk
        ulonglong2 v1 = col[64];
#pragma unroll
        for (int t = 0; t < 16; ++t) {
            ulonglong2 v2 = col[(t + 2) * 64];
            fma2(acc[t], w0a, v0.x);
            fma2(acc[t], w0b, v0.y);
            fma2(acc[t], w1a, v1.x);
            fma2(acc[t], w1b, v1.y);
            fma2(acc[t], w2a, v2.x);
            fma2(acc[t], w2b, v2.y);
            v0 = v1; v1 = v2;
        }
    }
    __syncthreads();   // done reading p; reuse smbuf as y[32][129]

    float btv = btmp[o];
    float* shy = (float*)smbuf;
    {
        const float* resp = g_res + ((size_t)(b * Tv) * Nv + n) * Hv + o;
#pragma unroll
        for (int t = 0; t < 16; ++t) {
            float y0, y1; unpack2(acc[t], y0, y1);
            float h0 = gelu_exact(y0 + btv) + resp[(size_t)t * Nv * Hv];
            float h1 = gelu_exact(y1 + btv) + resp[(size_t)(t + 16) * Nv * Hv];
            shy[t * 129 + o] = h0;
            shy[(t + 16) * 129 + o] = h1;
        }
    }
    __syncthreads();

    if (o < 32) {
        int r = o;
        float s1 = 0.0f;
#pragma unroll 8
        for (int j = 0; j < 128; ++j) s1 += shy[r * 129 + j];
        float mu = s1 * (1.0f / 128.0f);
        float s2 = 0.0f;
#pragma unroll 8
        for (int j = 0; j < 128; ++j) {
            float d = shy[r * 129 + j] - mu;
            s2 += d * d;
        }
        smu[r] = mu;
        srs[r] = rsqrtf(s2 * (1.0f / 128.0f) + 1e-5f);
    }
    __syncthreads();

    float lw = lnw[o], lb = lnb[o];
    float* op = out + ((size_t)(b * Tv) * Nv + n) * Hv + o;
#pragma unroll
    for (int t = 0; t < 32; ++t) {
        float v = shy[t * 129 + o];
        op[(size_t)t * Nv * Hv] = (v - smu[t]) * srs[t] * lw + lb;
    }
}

// ---------------- launch ----------------
extern "C" void kernel_launch(void* const* d_in, const int* in_sizes, int n_in,
                              void* d_out, int out_size) {
    const float* x   = (const float*)d_in[0];
    const void*  ei  = d_in[1];
    const float* ew  = (const float*)d_in[2];
    const float* Wg  = (const float*)d_in[3];
    const float* bg  = (const float*)d_in[4];
    const float* Wt  = (const float*)d_in[5];
    const float* btm = (const float*)d_in[6];
    const float* lnw = (const float*)d_in[7];
    const float* lnb = (const float*)d_in[8];
    const float* Wr  = (const float*)d_in[9];
    const float* br  = (const float*)d_in[10];
    float* out = (float*)d_out;

    cudaFuncSetAttribute(k_gcn, cudaFuncAttributeMaxDynamicSharedMemorySize, 64000);

    k_inproj  <<<1000, 128>>>(x, Wg, Wr, br);          // #1
    p_deg     <<<63 + 384, 128>>>(ei, ew, Wt);         // #2
    p_scanfill<<<1, 512>>>(ei, ew);                    // #3
    k_gcn     <<<dim3(BT, 4), 128, 64000>>>(bg);       // #4  <- profiled
    k_conv    <<<4000, 128>>>(btm, lnw, lnb, out);     // #5
}

// round 16
// speedup vs baseline: 1.5251x; 1.5251x over previous
#include <cuda_runtime.h>
#include <math.h>

#define Bv  8
#define Tv  32
#define Nv  500
#define Fv  64
#define Hv  128
#define Ev  8000
#define BT  256            // B*T
#define BTN 128000         // B*T*N
#define NNZ (Ev + Nv)

// ---------------- scratch (static device globals: allowed) ----------------
__device__ float  g_xf [BTN * Hv];   // x @ W_gcn            (bt, n, h)
__device__ float  g_res[BTN * Hv];   // x @ W_res + b_res    (bt, n, h)
__device__ float  g_hg [BTN * Hv];   // gelu(gcn agg + b)    (bt, n, h)
__device__ float  g_wt [384 * Hv];   // W_temp transposed: [(i*3+k)][o]
__device__ int    g_rowptr[Nv + 1];
__device__ float2 g_ev[NNZ];         // {norm, __int_as_float(src)} CSR by dst

// ---------------- helpers ----------------
__device__ __forceinline__ unsigned long long pack2(float lo, float hi) {
    unsigned long long r;
    asm("mov.b64 %0, {%1, %2};" : "=l"(r) : "f"(lo), "f"(hi));
    return r;
}
__device__ __forceinline__ void unpack2(unsigned long long v, float& lo, float& hi) {
    asm("mov.b64 {%0, %1}, %2;" : "=f"(lo), "=f"(hi) : "l"(v));
}
__device__ __forceinline__ void fma2(unsigned long long& d, unsigned long long a,
                                     unsigned long long b) {
    asm("fma.rn.f32x2 %0, %1, %2, %0;" : "+l"(d) : "l"(a), "l"(b));
}
__device__ __forceinline__ float gelu_exact(float x) {
    return 0.5f * x * (1.0f + erff(x * 0.7071067811865476f));
}
__device__ __forceinline__ int detect64(const void* ei) {
    const long long* p = (const long long*)ei;
    int ok64 = 1;
#pragma unroll
    for (int j = 0; j < 8; ++j) {
        long long v = p[j];
        if (v < 0 || v >= Nv) ok64 = 0;
    }
    return ok64;
}
__device__ __forceinline__ int load_idx(const void* ei, int i, int is64) {
    long long v;
    if (is64) v = ((const long long*)ei)[i];
    else      v = ((const int*)ei)[i];
    if (v < 0) v = 0;
    if (v >= Nv) v = Nv - 1;
    return (int)v;
}

// ---------------- P (launch #1): full CSR prep, single block --------------
// detect dtype + degree/count (smem atomics) + dinv + scan + CSR fill.
__global__ __launch_bounds__(512) void p_prep(
    const void* __restrict__ ei, const float* __restrict__ ew) {
    __shared__ float sdeg[Nv];
    __shared__ int   scnt[Nv];
    __shared__ float sdinv[Nv];
    __shared__ int   s[512];
    __shared__ int   sfill[Nv];
    __shared__ int   sis64;
    int tid = threadIdx.x;
    if (tid == 0) sis64 = detect64(ei);
    if (tid < Nv) { sdeg[tid] = 0.0f; scnt[tid] = 0; }
    __syncthreads();
    int is64 = sis64;

    for (int e = tid; e < Ev; e += 512) {
        int dst = load_idx(ei, Ev + e, is64);
        atomicAdd(&sdeg[dst], ew[e]);
        atomicAdd(&scnt[dst], 1);
    }
    __syncthreads();

    int c = 0;
    if (tid < Nv) {
        sdinv[tid] = rsqrtf(sdeg[tid] + 1.0f);   // + self loop weight
        c = scnt[tid] + 1;                       // + self loop edge
    }
    s[tid] = c;
    __syncthreads();
    for (int off = 1; off < 512; off <<= 1) {
        int v = (tid >= off) ? s[tid - off] : 0;
        __syncthreads();
        s[tid] += v;
        __syncthreads();
    }
    if (tid < Nv) {
        g_rowptr[tid + 1] = s[tid];
        sfill[tid] = s[tid] - c;
        if (tid == 0) g_rowptr[0] = 0;
    }
    __syncthreads();

    for (int e = tid; e < NNZ; e += 512) {
        int src, dst; float w;
        if (e < Ev) { src = load_idx(ei, e, is64); dst = load_idx(ei, Ev + e, is64); w = ew[e]; }
        else        { src = dst = e - Ev; w = 1.0f; }
        float v = sdinv[src] * w * sdinv[dst];
        int pos = atomicAdd(&sfill[dst], 1);
        if (pos >= 0 && pos < NNZ)
            g_ev[pos] = make_float2(v, __int_as_float(src));
    }
}

// ---------------- K2 (launch #2): input projections; tail blocks wtrans ---
__global__ __launch_bounds__(128) void k_inproj(
    const float* __restrict__ x, const float* __restrict__ Wg,
    const float* __restrict__ Wr, const float* __restrict__ br,
    const float* __restrict__ Wt) {
    if (blockIdx.x >= 1000) {
        int idx = (blockIdx.x - 1000) * 128 + threadIdx.x;   // < 49152
        if (idx < 128 * 384) {
            int o = idx / 384, m = idx % 384;
            g_wt[m * Hv + o] = Wt[o * 384 + m];
        }
        return;
    }
    __shared__ float sx[8][64];
    int h = threadIdx.x;
    unsigned long long wp[64];
#pragma unroll
    for (int i = 0; i < 64; ++i) wp[i] = pack2(Wg[i * Hv + h], Wr[i * Hv + h]);
    float brh = br[h];
    int row0 = blockIdx.x * 128;
#pragma unroll 1
    for (int c = 0; c < 16; ++c) {
        int rbase = row0 + c * 8;
        __syncthreads();
        for (int j = h; j < 512; j += 128)
            sx[j >> 6][j & 63] = x[(rbase + (j >> 6)) * Fv + (j & 63)];
        __syncthreads();
#pragma unroll
        for (int r = 0; r < 8; ++r) {
            unsigned long long acc = 0ULL;
#pragma unroll
            for (int i = 0; i < 64; i += 4) {
                float4 xv = *(const float4*)&sx[r][i];
                fma2(acc, pack2(xv.x, xv.x), wp[i + 0]);
                fma2(acc, pack2(xv.y, xv.y), wp[i + 1]);
                fma2(acc, pack2(xv.z, xv.z), wp[i + 2]);
                fma2(acc, pack2(xv.w, xv.w), wp[i + 3]);
            }
            float ag, ar; unpack2(acc, ag, ar);
            int row = rbase + r;
            g_xf [row * Hv + h] = ag;
            g_res[row * Hv + h] = ar + brh;
        }
    }
}

// ---------------- K3 (launch #3): GCN channel-quad gather (R14 best) ------
__global__ __launch_bounds__(128) void k_gcn(const float* __restrict__ bg) {
    __shared__ __align__(16) float4 sxf4[Nv * 4];   // 32000 B
    int bt = blockIdx.x;
    int hbase = blockIdx.y * 16;
    int tid = threadIdx.x;
    const float4* xsrc4 = (const float4*)(g_xf + (size_t)bt * (Nv * Hv));
    int c4base = hbase >> 2;
    for (int idx = tid; idx < Nv * 4; idx += 128) {
        int n = idx >> 2, c4 = idx & 3;
        sxf4[idx] = xsrc4[n * 32 + c4base + c4];
    }
    __syncthreads();
    int hh4 = tid & 3;               // channel quad within tile
    int ns = tid >> 2;               // 0..31
    int ch = hbase + 4 * hh4;
    float4 bgv = *(const float4*)(bg + ch);
    float4* dst4 = (float4*)(g_hg + (size_t)bt * (Nv * Hv));
    const ulonglong2* sxp = (const ulonglong2*)sxf4;
    for (int n = ns; n < Nv; n += 32) {
        int rs = g_rowptr[n], re = g_rowptr[n + 1];
        unsigned long long accA = 0ULL, accB = 0ULL;
        int e = rs;
        for (; e + 1 < re; e += 2) {
            float2 ev0 = g_ev[e];
            float2 ev1 = g_ev[e + 1];
            ulonglong2 v0 = sxp[__float_as_int(ev0.y) * 4 + hh4];
            ulonglong2 v1 = sxp[__float_as_int(ev1.y) * 4 + hh4];
            unsigned long long w0 = pack2(ev0.x, ev0.x);
            unsigned long long w1 = pack2(ev1.x, ev1.x);
            fma2(accA, w0, v0.x);
            fma2(accB, w0, v0.y);
            fma2(accA, w1, v1.x);
            fma2(accB, w1, v1.y);
        }
        if (e < re) {
            float2 ev0 = g_ev[e];
            ulonglong2 v0 = sxp[__float_as_int(ev0.y) * 4 + hh4];
            unsigned long long w0 = pack2(ev0.x, ev0.x);
            fma2(accA, w0, v0.x);
            fma2(accB, w0, v0.y);
        }
        float a0, a1, a2, a3;
        unpack2(accA, a0, a1);
        unpack2(accB, a2, a3);
        float4 r;
        r.x = gelu_exact(a0 + bgv.x);
        r.y = gelu_exact(a1 + bgv.y);
        r.z = gelu_exact(a2 + bgv.z);
        r.w = gelu_exact(a3 + bgv.w);
        dst4[n * 32 + (ch >> 2)] = r;
    }
}

// ---------------- K4 (launch #4, PROFILED): conv + gelu + res + LN --------
// v4 (R11 best): ONE (b,n) per block; t-dim packed into f32x2 lanes (t, t+16).
__global__ __launch_bounds__(128) void k_conv(
    const float* __restrict__ btmp,
    const float* __restrict__ lnw, const float* __restrict__ lnb,
    float* __restrict__ out) {
    __shared__ __align__(16) char smbuf[18432];
    __shared__ float smu[32], srs[32];
    int o = threadIdx.x;
    int bn = blockIdx.x;
    int b = bn / Nv, n = bn % Nv;

    // ---- stage packed input pairs ----
    {
        float xv[32];
        const float* src = g_hg + ((size_t)(b * Tv) * Nv + n) * Hv + o;
#pragma unroll
        for (int t = 0; t < 32; ++t) xv[t] = src[(size_t)t * Nv * Hv];
        float2* sp = (float2*)smbuf;          // [s][128]
#pragma unroll
        for (int s = 0; s < 18; ++s) {
            float lo = (s == 0)  ? 0.0f : xv[s - 1];
            float hi = (s == 17) ? 0.0f : xv[s + 15];
            sp[s * 128 + o] = make_float2(lo, hi);
        }
    }
    __syncthreads();

    unsigned long long acc[16];
#pragma unroll
    for (int t = 0; t < 16; ++t) acc[t] = 0ULL;

    const float* wtp = g_wt + o;               // [(m)][o], lane-coalesced
    const ulonglong2* colbase = (const ulonglong2*)smbuf;   // [s][64]
#pragma unroll 1
    for (int q = 0; q < 64; ++q) {             // i = 2q, 2q+1
        int m = q * 6;
        float wa0 = wtp[(m + 0) * Hv];
        float wa1 = wtp[(m + 1) * Hv];
        float wa2 = wtp[(m + 2) * Hv];
        float wb0 = wtp[(m + 3) * Hv];
        float wb1 = wtp[(m + 4) * Hv];
        float wb2 = wtp[(m + 5) * Hv];
        unsigned long long w0a = pack2(wa0, wa0), w1a = pack2(wa1, wa1),
                           w2a = pack2(wa2, wa2);
        unsigned long long w0b = pack2(wb0, wb0), w1b = pack2(wb1, wb1),
                           w2b = pack2(wb2, wb2);
        const ulonglong2* col = colbase + q;    // stride 64 per s
        ulonglong2 v0 = col[0];                 // s = t + kk
        ulonglong2 v1 = col[64];
#pragma unroll
        for (int t = 0; t < 16; ++t) {
            ulonglong2 v2 = col[(t + 2) * 64];
            fma2(acc[t], w0a, v0.x);
            fma2(acc[t], w0b, v0.y);
            fma2(acc[t], w1a, v1.x);
            fma2(acc[t], w1b, v1.y);
            fma2(acc[t], w2a, v2.x);
            fma2(acc[t], w2b, v2.y);
            v0 = v1; v1 = v2;
        }
    }
    __syncthreads();   // done reading p; reuse smbuf as y[32][129]

    float btv = btmp[o];
    float* shy = (float*)smbuf;
    {
        const float* resp = g_res + ((size_t)(b * Tv) * Nv + n) * Hv + o;
#pragma unroll
        for (int t = 0; t < 16; ++t) {
            float y0, y1; unpack2(acc[t], y0, y1);
            float h0 = gelu_exact(y0 + btv) + resp[(size_t)t * Nv * Hv];
            float h1 = gelu_exact(y1 + btv) + resp[(size_t)(t + 16) * Nv * Hv];
            shy[t * 129 + o] = h0;
            shy[(t + 16) * 129 + o] = h1;
        }
    }
    __syncthreads();

    if (o < 32) {
        int r = o;
        float s1 = 0.0f;
#pragma unroll 8
        for (int j = 0; j < 128; ++j) s1 += shy[r * 129 + j];
        float mu = s1 * (1.0f / 128.0f);
        float s2 = 0.0f;
#pragma unroll 8
        for (int j = 0; j < 128; ++j) {
            float d = shy[r * 129 + j] - mu;
            s2 += d * d;
        }
        smu[r] = mu;
        srs[r] = rsqrtf(s2 * (1.0f / 128.0f) + 1e-5f);
    }
    __syncthreads();

    float lw = lnw[o], lb = lnb[o];
    float* op = out + ((size_t)(b * Tv) * Nv + n) * Hv + o;
#pragma unroll
    for (int t = 0; t < 32; ++t) {
        float v = shy[t * 129 + o];
        op[(size_t)t * Nv * Hv] = (v - smu[t]) * srs[t] * lw + lb;
    }
}

// ---------------- launch ----------------
extern "C" void kernel_launch(void* const* d_in, const int* in_sizes, int n_in,
                              void* d_out, int out_size) {
    const float* x   = (const float*)d_in[0];
    const void*  ei  = d_in[1];
    const float* ew  = (const float*)d_in[2];
    const float* Wg  = (const float*)d_in[3];
    const float* bg  = (const float*)d_in[4];
    const float* Wt  = (const float*)d_in[5];
    const float* btm = (const float*)d_in[6];
    const float* lnw = (const float*)d_in[7];
    const float* lnb = (const float*)d_in[8];
    const float* Wr  = (const float*)d_in[9];
    const float* br  = (const float*)d_in[10];
    float* out = (float*)d_out;

    p_prep  <<<1, 512>>>(ei, ew);                         // #1
    k_inproj<<<1384, 128>>>(x, Wg, Wr, br, Wt);           // #2 (+wtrans tail)
    k_gcn   <<<dim3(BT, 8), 128>>>(bg);                   // #3
    k_conv  <<<4000, 128>>>(btm, lnw, lnb, out);          // #4  <- profiled
}